// round 10
// baseline (speedup 1.0000x reference)
#include <cuda_runtime.h>
#include <math.h>

namespace {

using u64 = unsigned long long;

constexpr int B      = 4096;
constexpr int NHID   = 512;
constexpr int BR     = 32;
constexpr int NG2    = 1024;
constexpr int WSLICE = NHID * BR;
constexpr int MAXIT  = 2048;
constexpr int NIT0   = 512;          // level-0 items (batch 8, static)

// ---- persistent scratch ----
__device__ int   g_cnt[NG2];         // zeroed by hs_combine each run
__device__ int   g_run[NG2];         // zeroed by hs_combine each run
__device__ int   g_off[NG2 + 1];
__device__ int   g_perm[B];
__device__ int2  g_items[MAXIT];     // {start | count<<16, node}  (L1 then L2)
__device__ int   g_nitems;           // L1+L2 item count
__device__ float g_q0[B];
__device__ float g_q1[B];
__device__ float g_q2[B];

// ---- f32x2 helpers (PTX-only packed FMA) ----
__device__ __forceinline__ u64 fma2(u64 a, u64 b, u64 c) {
    u64 d; asm("fma.rn.f32x2 %0, %1, %2, %3;" : "=l"(d) : "l"(a), "l"(b), "l"(c));
    return d;
}
__device__ __forceinline__ u64 add2(u64 a, u64 b) {
    u64 d; asm("add.rn.f32x2 %0, %1, %2;" : "=l"(d) : "l"(a), "l"(b));
    return d;
}
__device__ __forceinline__ u64 dup2(float x) {
    u64 d; asm("mov.b64 %0, {%1, %1};" : "=l"(d) : "r"(__float_as_uint(x)));
    return d;
}
__device__ __forceinline__ float lo32(u64 a) { return __uint_as_float((unsigned)a); }
__device__ __forceinline__ float hi32(u64 a) { return __uint_as_float((unsigned)(a >> 32)); }

__device__ __forceinline__ int warp_incl_scan(int v) {
    int lane = threadIdx.x & 31;
    #pragma unroll
    for (int o = 1; o < 32; o <<= 1) {
        int n = __shfl_up_sync(0xffffffffu, v, o);
        if (lane >= o) v += n;
    }
    return v;
}

// ================= K1: histogram (grid-wide) =================
__global__ void hs_hist(const int* __restrict__ labels)
{
    int i = blockIdx.x * blockDim.x + threadIdx.x;   // 16 x 256
    atomicAdd(&g_cnt[labels[i] >> 5], 1);
}

// ================= K2: scan + item build (1 block, 1024 threads) ===========
__global__ __launch_bounds__(1024)
void hs_scan()
{
    __shared__ int sA[33];
    __shared__ int sB[33];
    __shared__ int soff[NG2 + 1];
    __shared__ int s_tot1;

    const int tid  = threadIdx.x;
    const int lane = tid & 31;
    const int w    = tid >> 5;

    const int c = g_cnt[tid];

    // scan 1: exclusive group offsets
    {
        int inc = warp_incl_scan(c);
        if (lane == 31) sA[w] = inc;
        __syncthreads();
        if (w == 0) { int t = sA[lane]; int ti = warp_incl_scan(t); sA[lane] = ti - t; }
        __syncthreads();
        int off = inc - c + sA[w];
        soff[tid] = off;
        g_off[tid] = off;
        if (tid == NG2 - 1) { soff[NG2] = off + c; g_off[NG2] = off + c; }
    }
    __syncthreads();
    const int off = soff[tid];

    // scan 2: level-2 item offsets (batch 8 per leaf group)
    const int nit2 = (c + 7) >> 3;
    int ioff2, tot2;
    {
        int inc2 = warp_incl_scan(nit2);
        if (lane == 31) sB[w] = inc2;
        __syncthreads();
        if (w == 0) {
            int t = sB[lane]; int ti = warp_incl_scan(t);
            sB[lane] = ti - t;
            if (lane == 31) sB[32] = ti;
        }
        __syncthreads();
        ioff2 = inc2 - nit2 + sB[w];
        tot2  = sB[32];
    }

    // L1 items (32 groups of 32 leaf groups), batch 8
    if (tid < 32) {
        int st1 = soff[tid * 32];
        int c1  = soff[(tid + 1) * 32] - st1;
        int nit1 = (c1 + 7) >> 3;
        int i1 = warp_incl_scan(nit1);
        int it1off = i1 - nit1;
        int tot1 = __shfl_sync(0xffffffffu, i1, 31);
        if (tid == 0) s_tot1 = tot1;
        for (int k = 0; k < nit1; k++) {
            int cc = min(8, c1 - 8 * k);
            g_items[it1off + k] = make_int2((st1 + 8 * k) | (cc << 16), 1 + tid);
        }
    }
    __syncthreads();
    const int tot1 = s_tot1;

    // L2 items, batch 8
    for (int k = 0; k < nit2; k++) {
        int cc = min(8, c - 8 * k);
        g_items[tot1 + ioff2 + k] = make_int2((off + 8 * k) | (cc << 16), 33 + tid);
    }

    if (tid == 0) g_nitems = tot1 + tot2;
}

// ================= K3: scatter (grid-wide) =================
__global__ void hs_scatter(const int* __restrict__ labels)
{
    int i = blockIdx.x * blockDim.x + threadIdx.x;   // 16 x 256
    int g = labels[i] >> 5;
    int pos = g_off[g] + atomicAdd(&g_run[g], 1);
    g_perm[pos] = i;
}

// ============ main: one warp per item, batch 8, W software-pipelined ========
__global__ __launch_bounds__(128)
void hs_main(const float* __restrict__ inputs,
             const int*   __restrict__ labels,
             const float* __restrict__ W)
{
    const int lane = threadIdx.x & 31;
    const int cg   = lane & 7;      // 4-column group
    const int hs   = lane >> 3;     // h-stripe within 16-chunk
    const int gw   = (blockIdx.x << 2) + (threadIdx.x >> 5);
    const int nw   = gridDim.x << 2;
    const int nit  = NIT0 + g_nitems;

    for (int it = gw; it < nit; it += nw) {
        int start, count, node;
        bool use_perm;
        if (it < NIT0) { start = it * 8; count = 8; node = 0; use_perm = false; }
        else {
            const int2 t = g_items[it - NIT0];
            start = t.x & 0xffff; count = t.x >> 16; node = t.y;
            use_perm = true;
        }

        int shift;
        float* qdst;
        if (node == 0)      { shift = 10; qdst = g_q0; }
        else if (node < 33) { shift = 5;  qdst = g_q1; }
        else                { shift = 0;  qdst = g_q2; }

        // per-lane sample: lane s (<count) owns sample s; others clamp
        const int pos   = start + ((lane < count) ? lane : (count - 1));
        const int myidx = use_perm ? g_perm[pos] : pos;
        const int mylab = labels[myidx];

        // broadcast the 8 x row offsets to all lanes (once per item)
        int xo[8];
        #pragma unroll
        for (int s = 0; s < 8; s++)
            xo[s] = __shfl_sync(0xffffffffu, myidx, s) * NHID;

        const float* __restrict__ Wn = W + (size_t)node * WSLICE + cg * 4;

        u64 acc0[8], acc1[8];       // (c0,c1),(c2,c3) packed per sample
        #pragma unroll
        for (int s = 0; s < 8; s++) { acc0[s] = 0ull; acc1[s] = 0ull; }

        // software pipeline: W for iteration 0 preloaded
        ulonglong2 wv[4];
        #pragma unroll
        for (int j = 0; j < 4; j++)
            wv[j] = *(const ulonglong2*)&Wn[(hs * 4 + j) * BR];

        #pragma unroll 2
        for (int hb = 0; hb < NHID; hb += 16) {
            const int h0 = hb + hs * 4;

            // stage x for this iteration (L2-hot)
            float4 xv[8];
            #pragma unroll
            for (int s = 0; s < 8; s++)
                xv[s] = *(const float4*)&inputs[xo[s] + h0];

            // prefetch next iteration's W (DRAM-streamed) before the FMAs
            ulonglong2 wn[4];
            const bool more = (hb + 16) < NHID;
            #pragma unroll
            for (int j = 0; j < 4; j++)
                if (more) wn[j] = *(const ulonglong2*)&Wn[(h0 + 16 + j) * BR];

            #pragma unroll
            for (int j = 0; j < 4; j++) {
                #pragma unroll
                for (int s = 0; s < 8; s++) {
                    const u64 xd = dup2((&xv[s].x)[j]);
                    acc0[s] = fma2(wv[j].x, xd, acc0[s]);
                    acc1[s] = fma2(wv[j].y, xd, acc1[s]);
                }
            }
            #pragma unroll
            for (int j = 0; j < 4; j++) wv[j] = wn[j];
        }

        // reduce over the 4 h-stripes (lanes cg, cg+8, cg+16, cg+24)
        #pragma unroll
        for (int o = 8; o <= 16; o <<= 1)
            #pragma unroll
            for (int s = 0; s < 8; s++) {
                acc0[s] = add2(acc0[s], __shfl_xor_sync(0xffffffffu, acc0[s], o));
                acc1[s] = add2(acc1[s], __shfl_xor_sync(0xffffffffu, acc1[s], o));
            }

        // per-sample softmax across the 8 column-group lanes
        #pragma unroll
        for (int s = 0; s < 8; s++) {
            const int st = (__shfl_sync(0xffffffffu, mylab, s) >> shift) & 31; // warp-uniform
            const float a0 = lo32(acc0[s]), a1 = hi32(acc0[s]);
            const float a2 = lo32(acc1[s]), a3 = hi32(acc1[s]);
            float mx = fmaxf(fmaxf(a0, a1), fmaxf(a2, a3));
            #pragma unroll
            for (int o = 1; o < 8; o <<= 1)
                mx = fmaxf(mx, __shfl_xor_sync(0xffffffffu, mx, o));
            float e = __expf(a0 - mx) + __expf(a1 - mx) + __expf(a2 - mx) + __expf(a3 - mx);
            #pragma unroll
            for (int o = 1; o < 8; o <<= 1)
                e += __shfl_xor_sync(0xffffffffu, e, o);
            const float lse = mx + __logf(e);
            // selected logit lives in lane (st>>2) of each 8-lane group
            const int r = st & 3;
            const float v = (r == 0) ? a0 : (r == 1) ? a1 : (r == 2) ? a2 : a3;
            const float sel = __shfl_sync(0xffffffffu, v, (lane & 24) | (st >> 2));
            if (lane == s && lane < count) qdst[myidx] = sel - lse;
        }
    }
}

// ================= combine + reset counters for next replay =================
__global__ void hs_combine(float* __restrict__ out)
{
    int i = blockIdx.x * blockDim.x + threadIdx.x;   // 16 x 256
    out[i] = __expf(g_q0[i] + g_q1[i] + g_q2[i]);
    if (i < NG2)          g_cnt[i] = 0;
    else if (i < 2 * NG2) g_run[i - NG2] = 0;
}

} // namespace

extern "C" void kernel_launch(void* const* d_in, const int* in_sizes, int n_in,
                              void* d_out, int out_size)
{
    const float* inputs = (const float*)d_in[0];
    const int*   labels = (const int*)d_in[1];
    const float* W      = (const float*)d_in[2];
    float*       out    = (float*)d_out;

    hs_hist   <<<16, 256>>>(labels);
    hs_scan   <<<1, 1024>>>();
    hs_scatter<<<16, 256>>>(labels);
    hs_main   <<<592, 128>>>(inputs, labels, W);
    hs_combine<<<16, 256>>>(out);
}